// round 8
// baseline (speedup 1.0000x reference)
#include <cuda_runtime.h>
#include <cuda_bf16.h>
#include <mma.h>

using namespace nvcuda;

// Problem constants
#define NC     64          // channels
#define SS     3136        // 56*56
#define NIMG   128
#define MTOT   (NIMG*SS)   // 401408
#define KT     64          // s-tile width
#define TILES  (NIMG*49)   // 6272 tiles of 64 columns
#define GBLK   448         // gram grid (6272/448 = 14 tiles/block, exact)
#define WBLK   784         // whiten grid (6272/784 = 8 tiles/block, exact)
#define BPITCH 72          // bf16 smem pitch (mult of 8 elems = 16B)
#define EPSF   1e-3f

// Scratch (static device globals: allocation-free)
__device__ float          g_partials[GBLK][4160]; // 4096 gram + 64 channel sums
__device__ float          g_G[4160];
__device__ float          g_mean[NC];
__device__ __nv_bfloat16  g_E[NC*NC];             // wm - I, row-major [c_out][c_in]
__device__ __nv_bfloat16  g_Vfrag[NC*16];         // A-fragment源: col0 = v = -m - E@m
__device__ __nv_bfloat16  g_Ones[16*16];          // B-fragment源: row0 = 1

// ---------------------------------------------------------------------------
// Kernel 1: partial Gram + channel sums (raw x).
// Double-buffered bf16 tile, ONE __syncthreads per tile.
// ---------------------------------------------------------------------------
__global__ __launch_bounds__(256) void gram_kernel(const float* __restrict__ X) {
    __shared__ __nv_bfloat16 tb[2][NC * BPITCH];
    __shared__ float ssum[NC];

    const int t = threadIdx.x, b = blockIdx.x;
    const int warp = t >> 5;
    const int row = t >> 2;          // channel row 0..63
    const int c4  = (t & 3) * 4;     // first float4 index

    const int r0 = (warp >> 1) * 16;     // output row block (strip)
    const int q0 = (warp & 1) * 32;      // output col base

    wmma::fragment<wmma::accumulator, 16, 16, 16, float> acc[2];
    wmma::fill_fragment(acc[0], 0.0f);
    wmma::fill_fragment(acc[1], 0.0f);

    float lsum = 0.0f;

    // prologue: tile 0 -> tb[0]
    {
        const int n  = b / 49;
        const int s0 = (b % 49) * KT;
        const float4* src = (const float4*)(X + (size_t)n * NC * SS + (size_t)row * SS + s0);
        #pragma unroll
        for (int j = 0; j < 4; ++j) {
            float4 v = src[c4 + j];
            lsum += v.x + v.y + v.z + v.w;
            __nv_bfloat162* dst = (__nv_bfloat162*)&tb[0][row * BPITCH + (c4 + j) * 4];
            dst[0] = __floats2bfloat162_rn(v.x, v.y);
            dst[1] = __floats2bfloat162_rn(v.z, v.w);
        }
    }
    __syncthreads();

    for (int it = 0; it < 14; ++it) {
        const int buf = it & 1;

        // load next tile (in flight across the MMA section)
        float4 w[4];
        if (it < 13) {
            const int T  = b + (it + 1) * GBLK;
            const int n  = T / 49;
            const int s0 = (T % 49) * KT;
            const float4* src = (const float4*)(X + (size_t)n * NC * SS + (size_t)row * SS + s0);
            #pragma unroll
            for (int j = 0; j < 4; ++j) w[j] = src[c4 + j];
        }

        #pragma unroll
        for (int k = 0; k < 4; ++k) {
            wmma::fragment<wmma::matrix_a, 16, 16, 16, __nv_bfloat16, wmma::row_major> fa;
            wmma::fragment<wmma::matrix_b, 16, 16, 16, __nv_bfloat16, wmma::col_major> fb0, fb1;
            wmma::load_matrix_sync(fa,  &tb[buf][r0 * BPITCH + k * 16], BPITCH);
            wmma::load_matrix_sync(fb0, &tb[buf][q0 * BPITCH + k * 16], BPITCH);
            wmma::load_matrix_sync(fb1, &tb[buf][(q0 + 16) * BPITCH + k * 16], BPITCH);
            wmma::mma_sync(acc[0], fa, fb0, acc[0]);
            wmma::mma_sync(acc[1], fa, fb1, acc[1]);
        }

        if (it < 13) {
            #pragma unroll
            for (int j = 0; j < 4; ++j) {
                lsum += w[j].x + w[j].y + w[j].z + w[j].w;
                __nv_bfloat162* dst = (__nv_bfloat162*)&tb[buf ^ 1][row * BPITCH + (c4 + j) * 4];
                dst[0] = __floats2bfloat162_rn(w[j].x, w[j].y);
                dst[1] = __floats2bfloat162_rn(w[j].z, w[j].w);
            }
        }
        __syncthreads();
    }

    lsum += __shfl_down_sync(0xffffffffu, lsum, 2);
    lsum += __shfl_down_sync(0xffffffffu, lsum, 1);
    if ((t & 3) == 0) ssum[row] = lsum;
    __syncthreads();

    wmma::store_matrix_sync(&g_partials[b][r0 * 64 + q0],      acc[0], 64, wmma::mem_row_major);
    wmma::store_matrix_sync(&g_partials[b][r0 * 64 + q0 + 16], acc[1], 64, wmma::mem_row_major);
    if (t < NC) g_partials[b][4096 + t] = ssum[t];
}

// ---------------------------------------------------------------------------
// Kernel 2: reduce 448 partials -> g_G  (float4 vectorized)
// ---------------------------------------------------------------------------
__global__ __launch_bounds__(256) void reduce_kernel() {
    const int i4 = blockIdx.x * blockDim.x + threadIdx.x;
    if (i4 < 1040) {  // 4160/4
        float4 s = make_float4(0.f, 0.f, 0.f, 0.f);
        #pragma unroll 4
        for (int b = 0; b < GBLK; ++b) {
            float4 v = ((const float4*)g_partials[b])[i4];
            s.x += v.x; s.y += v.y; s.z += v.z; s.w += v.w;
        }
        ((float4*)g_G)[i4] = s;
    }
}

// ---------------------------------------------------------------------------
// Kernel 3: stats: sigma -> Taylor inverse-sqrt -> E (bf16), v = -m - E@m,
// and the two constant wmma fragments (Vfrag, Ones).
// ---------------------------------------------------------------------------
__global__ __launch_bounds__(256) void stats_kernel() {
    __shared__ float sP[4096];
    __shared__ float sQ[4096];
    __shared__ float smean[NC];
    __shared__ float sMu, sRs;

    const int t = threadIdx.x;
    const float invm = 1.0f / (float)MTOT;

    if (t < NC) {
        float mn = g_G[4096 + t] * invm;
        smean[t] = mn;
        g_mean[t] = mn;
    }
    __syncthreads();

    for (int i = t; i < 4096; i += 256) {
        int r = i >> 6, c = i & 63;
        sP[i] = g_G[i] * invm - smean[r] * smean[c] + ((r == c) ? EPSF : 0.0f);
    }
    __syncthreads();

    if (t == 0) {
        float tr = 0.0f;
        for (int i = 0; i < NC; ++i) tr += sP[i * 65];
        float mu = tr / (float)NC;
        sMu = mu;
        float rs = rsqrtf(mu);
        rs = rs * (1.5f - 0.5f * mu * rs * rs);
        sRs = rs;
    }
    __syncthreads();

    const float invmu = 1.0f / sMu;
    for (int i = t; i < 4096; i += 256) {
        int r = i >> 6, c = i & 63;
        sP[i] = sP[i] * invmu - ((r == c) ? 1.0f : 0.0f);
    }
    __syncthreads();

    const int r0 = (t >> 4) * 4;
    const int c0 = (t & 15) * 4;
    {
        float a[4][4] = {};
        for (int k = 0; k < 64; ++k) {
            float pa[4], pb[4];
            #pragma unroll
            for (int i = 0; i < 4; ++i) pa[i] = sP[(r0 + i) * 64 + k];
            #pragma unroll
            for (int j = 0; j < 4; ++j) pb[j] = sP[k * 64 + c0 + j];
            #pragma unroll
            for (int i = 0; i < 4; ++i)
                #pragma unroll
                for (int j = 0; j < 4; ++j) a[i][j] += pa[i] * pb[j];
        }
        #pragma unroll
        for (int i = 0; i < 4; ++i)
            #pragma unroll
            for (int j = 0; j < 4; ++j) sQ[(r0 + i) * 64 + c0 + j] = a[i][j];
    }
    __syncthreads();

    const float rs = sRs;
    {
        float a[4][4] = {};  // Q@P block
        for (int k = 0; k < 64; ++k) {
            float pa[4], pb[4];
            #pragma unroll
            for (int i = 0; i < 4; ++i) pa[i] = sQ[(r0 + i) * 64 + k];
            #pragma unroll
            for (int j = 0; j < 4; ++j) pb[j] = sP[k * 64 + c0 + j];
            #pragma unroll
            for (int i = 0; i < 4; ++i)
                #pragma unroll
                for (int j = 0; j < 4; ++j) a[i][j] += pa[i] * pb[j];
        }
        #pragma unroll
        for (int i = 0; i < 4; ++i) {
            #pragma unroll
            for (int j = 0; j < 4; ++j) {
                int idx = (r0 + i) * 64 + (c0 + j);
                float dlt = (r0 + i == c0 + j) ? 1.0f : 0.0f;
                float wmh = dlt - 0.5f * sP[idx] + 0.375f * sQ[idx] - 0.3125f * a[i][j];
                float ef  = wmh * rs - dlt;       // E (fp32)
                g_E[idx] = __float2bfloat16(ef);
                sQ[idx]  = ef;                    // stash fp32 E for E@m
            }
        }
    }
    __syncthreads();

    // v = -m - E@m ; build constant fragments
    if (t < NC) {
        float s = 0.0f;
        for (int j = 0; j < NC; ++j) s += sQ[t * 64 + j] * smean[j];
        float v = -smean[t] - s;
        #pragma unroll
        for (int j = 0; j < 16; ++j)
            g_Vfrag[t * 16 + j] = __float2bfloat16(j == 0 ? v : 0.0f);
    }
    if (t >= 64 && t < 80) {
        int r = t - 64;
        #pragma unroll
        for (int j = 0; j < 16; ++j)
            g_Ones[r * 16 + j] = __float2bfloat16(r == 0 ? 1.0f : 0.0f);
    }
}

// ---------------------------------------------------------------------------
// Kernel 4: whiten  out = x + E@x + v   (v = -m - E@m)
//  - NO centering: bf16 tile is raw x
//  - identity path: accumulator initialized from global X (fp32, L1-hot)
//  - v folded in as a 5th MMA step with constant hoisted fragments
//  - direct store_matrix_sync to Y (128B contiguous per row across 2 accs)
//  - no scratch smem, 1 block barrier per tile, 3 CTAs/SM forced
// ---------------------------------------------------------------------------
__global__ __launch_bounds__(256, 3) void whiten_kernel(const float* __restrict__ X,
                                                        float* __restrict__ Y) {
    __shared__ __nv_bfloat16 tb[2][NC * BPITCH];

    const int t = threadIdx.x, b = blockIdx.x;
    const int warp = t >> 5;

    const int r0 = (warp >> 1) * 16;   // warp's output channel strip
    const int q0 = (warp & 1) * 32;    // warp's s base
    const int row = t >> 2;            // loader: channel row
    const int c4  = (t & 3) * 4;       // loader: first float4

    // hoisted constant fragments
    wmma::fragment<wmma::matrix_a, 16, 16, 16, __nv_bfloat16, wmma::row_major> fa[4], fav;
    wmma::fragment<wmma::matrix_b, 16, 16, 16, __nv_bfloat16, wmma::row_major> fbo;
    #pragma unroll
    for (int k = 0; k < 4; ++k)
        wmma::load_matrix_sync(fa[k], &g_E[r0 * 64 + k * 16], 64);
    wmma::load_matrix_sync(fav, &g_Vfrag[r0 * 16], 16);
    wmma::load_matrix_sync(fbo, g_Ones, 16);

    // prologue: tile 0 (raw) -> tb[0]
    {
        const int n  = b / 49;
        const int s0 = (b % 49) * KT;
        const float4* src = (const float4*)(X + (size_t)n * NC * SS + (size_t)row * SS + s0);
        #pragma unroll
        for (int j = 0; j < 4; ++j) {
            float4 v = src[c4 + j];
            __nv_bfloat162* dst = (__nv_bfloat162*)&tb[0][row * BPITCH + (c4 + j) * 4];
            dst[0] = __floats2bfloat162_rn(v.x, v.y);
            dst[1] = __floats2bfloat162_rn(v.z, v.w);
        }
    }
    __syncthreads();

    for (int it = 0; it < 8; ++it) {
        const int buf = it & 1;
        const int T  = b + it * WBLK;
        const int n  = T / 49;
        const int s0 = (T % 49) * KT;

        // load next tile (in flight across MMA)
        float4 w[4];
        if (it < 7) {
            const int Tn = b + (it + 1) * WBLK;
            const int nn = Tn / 49;
            const int sn = (Tn % 49) * KT;
            const float4* src = (const float4*)(X + (size_t)nn * NC * SS + (size_t)row * SS + sn);
            #pragma unroll
            for (int j = 0; j < 4; ++j) w[j] = src[c4 + j];
        }

        // accumulators initialized with the fp32 identity tile (L1-hot re-read)
        wmma::fragment<wmma::accumulator, 16, 16, 16, float> acc0, acc1;
        const float* Xt = X + (size_t)n * NC * SS + (size_t)r0 * SS + s0;
        wmma::load_matrix_sync(acc0, Xt + q0,      SS, wmma::mem_row_major);
        wmma::load_matrix_sync(acc1, Xt + q0 + 16, SS, wmma::mem_row_major);

        #pragma unroll
        for (int k = 0; k < 4; ++k) {
            wmma::fragment<wmma::matrix_b, 16, 16, 16, __nv_bfloat16, wmma::row_major> fb0, fb1;
            wmma::load_matrix_sync(fb0, &tb[buf][(k * 16) * BPITCH + q0], BPITCH);
            wmma::load_matrix_sync(fb1, &tb[buf][(k * 16) * BPITCH + q0 + 16], BPITCH);
            wmma::mma_sync(acc0, fa[k], fb0, acc0);
            wmma::mma_sync(acc1, fa[k], fb1, acc1);
        }
        // + v (per-row constant) via constant fragments
        wmma::mma_sync(acc0, fav, fbo, acc0);
        wmma::mma_sync(acc1, fav, fbo, acc1);

        // publish next tile
        if (it < 7) {
            #pragma unroll
            for (int j = 0; j < 4; ++j) {
                __nv_bfloat162* dst = (__nv_bfloat162*)&tb[buf ^ 1][row * BPITCH + (c4 + j) * 4];
                dst[0] = __floats2bfloat162_rn(w[j].x, w[j].y);
                dst[1] = __floats2bfloat162_rn(w[j].z, w[j].w);
            }
        }

        // direct store: out rows are 128B contiguous (acc0|acc1)
        float* Yt = Y + (size_t)n * NC * SS + (size_t)r0 * SS + s0;
        wmma::store_matrix_sync(Yt + q0,      acc0, SS, wmma::mem_row_major);
        wmma::store_matrix_sync(Yt + q0 + 16, acc1, SS, wmma::mem_row_major);

        __syncthreads();
    }
}

// ---------------------------------------------------------------------------
extern "C" void kernel_launch(void* const* d_in, const int* in_sizes, int n_in,
                              void* d_out, int out_size) {
    (void)in_sizes; (void)n_in; (void)out_size;
    const float* X = (const float*)d_in[0];
    float* Y = (float*)d_out;

    gram_kernel<<<GBLK, 256>>>(X);
    reduce_kernel<<<5, 256>>>();
    stats_kernel<<<1, 256>>>();
    whiten_kernel<<<WBLK, 256>>>(X, Y);
}

// round 9
// speedup vs baseline: 1.1082x; 1.1082x over previous
#include <cuda_runtime.h>
#include <cuda_bf16.h>
#include <mma.h>

using namespace nvcuda;

// Problem constants
#define NC     64          // channels
#define SS     3136        // 56*56
#define NIMG   128
#define MTOT   (NIMG*SS)   // 401408
#define KT     64          // s-tile width
#define TILES  (NIMG*49)   // 6272 tiles of 64 columns
#define GRID   296         // persistent grid: 148 SMs x 2 CTA/SM = one wave
#define BPITCH 72          // bf16 smem pitch (mult of 8 elems = 16B)
#define SPITCH 40          // fp32 scratch pitch: 40 words -> conflict-free LDS.128
#define EPSF   1e-3f

// Scratch (static device globals: allocation-free)
__device__ float          g_partials[GRID][4160]; // 4096 gram + 64 channel sums
__device__ float          g_G[4160];
__device__ float          g_mean[NC];
__device__ __nv_bfloat16  g_E[NC*NC];             // wm - I, row-major [c_out][c_in]

// ---------------------------------------------------------------------------
// Kernel 1: partial Gram + channel sums. Persistent grid (one wave at
// 2 CTA/SM), double-buffered bf16 tile, ONE __syncthreads per tile.
// ---------------------------------------------------------------------------
__global__ __launch_bounds__(256, 2) void gram_kernel(const float* __restrict__ X) {
    __shared__ __nv_bfloat16 tb[2][NC * BPITCH];
    __shared__ float ssum[NC];

    const int t = threadIdx.x, b = blockIdx.x;
    const int warp = t >> 5;
    const int row = t >> 2;          // channel row 0..63
    const int c4  = (t & 3) * 4;     // first float4 index

    const int r0 = (warp >> 1) * 16;     // output row block (strip)
    const int q0 = (warp & 1) * 32;      // output col base

    wmma::fragment<wmma::accumulator, 16, 16, 16, float> acc[2];
    wmma::fill_fragment(acc[0], 0.0f);
    wmma::fill_fragment(acc[1], 0.0f);

    float lsum = 0.0f;

    // prologue: tile b -> tb[0]
    {
        const int n  = b / 49;
        const int s0 = (b % 49) * KT;
        const float4* src = (const float4*)(X + (size_t)n * NC * SS + (size_t)row * SS + s0);
        #pragma unroll
        for (int j = 0; j < 4; ++j) {
            float4 v = src[c4 + j];
            lsum += v.x + v.y + v.z + v.w;
            __nv_bfloat162* dst = (__nv_bfloat162*)&tb[0][row * BPITCH + (c4 + j) * 4];
            dst[0] = __floats2bfloat162_rn(v.x, v.y);
            dst[1] = __floats2bfloat162_rn(v.z, v.w);
        }
    }
    __syncthreads();

    int buf = 0;
    for (int T = b; T < TILES; T += GRID, buf ^= 1) {
        const int Tn = T + GRID;
        const bool has = (Tn < TILES);

        // load next tile (in flight across the MMA section)
        float4 w[4];
        if (has) {
            const int n  = Tn / 49;
            const int s0 = (Tn % 49) * KT;
            const float4* src = (const float4*)(X + (size_t)n * NC * SS + (size_t)row * SS + s0);
            #pragma unroll
            for (int j = 0; j < 4; ++j) w[j] = src[c4 + j];
        }

        #pragma unroll
        for (int k = 0; k < 4; ++k) {
            wmma::fragment<wmma::matrix_a, 16, 16, 16, __nv_bfloat16, wmma::row_major> fa;
            wmma::fragment<wmma::matrix_b, 16, 16, 16, __nv_bfloat16, wmma::col_major> fb0, fb1;
            wmma::load_matrix_sync(fa,  &tb[buf][r0 * BPITCH + k * 16], BPITCH);
            wmma::load_matrix_sync(fb0, &tb[buf][q0 * BPITCH + k * 16], BPITCH);
            wmma::load_matrix_sync(fb1, &tb[buf][(q0 + 16) * BPITCH + k * 16], BPITCH);
            wmma::mma_sync(acc[0], fa, fb0, acc[0]);
            wmma::mma_sync(acc[1], fa, fb1, acc[1]);
        }

        if (has) {
            #pragma unroll
            for (int j = 0; j < 4; ++j) {
                lsum += w[j].x + w[j].y + w[j].z + w[j].w;
                __nv_bfloat162* dst = (__nv_bfloat162*)&tb[buf ^ 1][row * BPITCH + (c4 + j) * 4];
                dst[0] = __floats2bfloat162_rn(w[j].x, w[j].y);
                dst[1] = __floats2bfloat162_rn(w[j].z, w[j].w);
            }
        }
        __syncthreads();
    }

    lsum += __shfl_down_sync(0xffffffffu, lsum, 2);
    lsum += __shfl_down_sync(0xffffffffu, lsum, 1);
    if ((t & 3) == 0) ssum[row] = lsum;
    __syncthreads();

    wmma::store_matrix_sync(&g_partials[b][r0 * 64 + q0],      acc[0], 64, wmma::mem_row_major);
    wmma::store_matrix_sync(&g_partials[b][r0 * 64 + q0 + 16], acc[1], 64, wmma::mem_row_major);
    if (t < NC) g_partials[b][4096 + t] = ssum[t];
}

// ---------------------------------------------------------------------------
// Kernel 2: reduce GRID partials -> g_G  (float4 vectorized)
// ---------------------------------------------------------------------------
__global__ __launch_bounds__(256) void reduce_kernel() {
    const int i4 = blockIdx.x * blockDim.x + threadIdx.x;
    if (i4 < 1040) {  // 4160/4
        float4 s = make_float4(0.f, 0.f, 0.f, 0.f);
        #pragma unroll 4
        for (int b = 0; b < GRID; ++b) {
            float4 v = ((const float4*)g_partials[b])[i4];
            s.x += v.x; s.y += v.y; s.z += v.z; s.w += v.w;
        }
        ((float4*)g_G)[i4] = s;
    }
}

// ---------------------------------------------------------------------------
// Kernel 3: single-block stats: sigma -> Taylor inverse-sqrt -> E = wm - I (bf16)
// ---------------------------------------------------------------------------
__global__ __launch_bounds__(256) void stats_kernel() {
    __shared__ float sP[4096];
    __shared__ float sQ[4096];
    __shared__ float smean[NC];
    __shared__ float sMu, sRs;

    const int t = threadIdx.x;
    const float invm = 1.0f / (float)MTOT;

    if (t < NC) {
        float mn = g_G[4096 + t] * invm;
        smean[t] = mn;
        g_mean[t] = mn;
    }
    __syncthreads();

    for (int i = t; i < 4096; i += 256) {
        int r = i >> 6, c = i & 63;
        sP[i] = g_G[i] * invm - smean[r] * smean[c] + ((r == c) ? EPSF : 0.0f);
    }
    __syncthreads();

    if (t == 0) {
        float tr = 0.0f;
        for (int i = 0; i < NC; ++i) tr += sP[i * 65];
        float mu = tr / (float)NC;
        sMu = mu;
        float rs = rsqrtf(mu);
        rs = rs * (1.5f - 0.5f * mu * rs * rs);
        sRs = rs;
    }
    __syncthreads();

    const float invmu = 1.0f / sMu;
    for (int i = t; i < 4096; i += 256) {
        int r = i >> 6, c = i & 63;
        sP[i] = sP[i] * invmu - ((r == c) ? 1.0f : 0.0f);
    }
    __syncthreads();

    const int r0 = (t >> 4) * 4;
    const int c0 = (t & 15) * 4;
    {
        float a[4][4] = {};
        for (int k = 0; k < 64; ++k) {
            float pa[4], pb[4];
            #pragma unroll
            for (int i = 0; i < 4; ++i) pa[i] = sP[(r0 + i) * 64 + k];
            #pragma unroll
            for (int j = 0; j < 4; ++j) pb[j] = sP[k * 64 + c0 + j];
            #pragma unroll
            for (int i = 0; i < 4; ++i)
                #pragma unroll
                for (int j = 0; j < 4; ++j) a[i][j] += pa[i] * pb[j];
        }
        #pragma unroll
        for (int i = 0; i < 4; ++i)
            #pragma unroll
            for (int j = 0; j < 4; ++j) sQ[(r0 + i) * 64 + c0 + j] = a[i][j];
    }
    __syncthreads();

    const float rs = sRs;
    {
        float a[4][4] = {};  // Q@P block
        for (int k = 0; k < 64; ++k) {
            float pa[4], pb[4];
            #pragma unroll
            for (int i = 0; i < 4; ++i) pa[i] = sQ[(r0 + i) * 64 + k];
            #pragma unroll
            for (int j = 0; j < 4; ++j) pb[j] = sP[k * 64 + c0 + j];
            #pragma unroll
            for (int i = 0; i < 4; ++i)
                #pragma unroll
                for (int j = 0; j < 4; ++j) a[i][j] += pa[i] * pb[j];
        }
        #pragma unroll
        for (int i = 0; i < 4; ++i) {
            #pragma unroll
            for (int j = 0; j < 4; ++j) {
                int idx = (r0 + i) * 64 + (c0 + j);
                float dlt = (r0 + i == c0 + j) ? 1.0f : 0.0f;
                float wmh = dlt - 0.5f * sP[idx] + 0.375f * sQ[idx] - 0.3125f * a[i][j];
                g_E[idx] = __float2bfloat16(wmh * rs - dlt);
            }
        }
    }
}

// ---------------------------------------------------------------------------
// Kernel 4: whiten  out = xc + E @ xc   (R7 structure, persistent grid)
//  - E fragments hoisted (loaded ONCE from g_E)
//  - warp-matched ownership; centered fp32 xc in registers across the MMA
//  - correction via warp-private scratch (__syncwarp only)
//  - double-buffered bf16 tile, ONE block barrier per tile
// ---------------------------------------------------------------------------
__global__ __launch_bounds__(256, 2) void whiten_kernel(const float* __restrict__ X,
                                                        float* __restrict__ Y) {
    __shared__ __nv_bfloat16  tb[2][NC * BPITCH];      // bf16 centered tiles
    __shared__ float          scratch[8][16 * SPITCH]; // per-warp 16x32 corr
    __shared__ float          smean[NC];

    const int t = threadIdx.x, b = blockIdx.x;
    const int warp = t >> 5, lane = t & 31;

    if (t < NC) smean[t] = g_mean[t];
    __syncthreads();

    const int r0 = (warp >> 1) * 16;       // warp's output channel strip
    const int q0 = (warp & 1) * 32;        // warp's s base
    const int row  = r0 + (lane >> 1);     // this lane's channel row
    const int coff = q0 + (lane & 1) * 4;  // this lane's first float col (j adds 8j)
    const float mu = smean[row];

    // hoisted E fragments: loaded once, directly from global
    wmma::fragment<wmma::matrix_a, 16, 16, 16, __nv_bfloat16, wmma::row_major> fa[4];
    #pragma unroll
    for (int k = 0; k < 4; ++k)
        wmma::load_matrix_sync(fa[k], &g_E[r0 * 64 + k * 16], 64);

    const float* scp = &scratch[warp][(lane >> 1) * SPITCH + (lane & 1) * 4];

    // prologue: tile b -> centered regs + tb[0]
    float4 cur[4];
    {
        const int n  = b / 49;
        const int s0 = (b % 49) * KT;
        const float* src = X + (size_t)n * NC * SS + (size_t)row * SS + s0 + coff;
        #pragma unroll
        for (int j = 0; j < 4; ++j) {
            float4 v = *(const float4*)(src + 8 * j);
            v.x -= mu; v.y -= mu; v.z -= mu; v.w -= mu;
            cur[j] = v;
            __nv_bfloat162* dst = (__nv_bfloat162*)&tb[0][row * BPITCH + coff + 8 * j];
            dst[0] = __floats2bfloat162_rn(v.x, v.y);
            dst[1] = __floats2bfloat162_rn(v.z, v.w);
        }
    }
    __syncthreads();

    int buf = 0;
    for (int T = b; T < TILES; T += GRID, buf ^= 1) {
        const int n  = T / 49;
        const int s0 = (T % 49) * KT;
        const int Tn = T + GRID;
        const bool has = (Tn < TILES);

        // load next tile (in flight across MMA)
        float4 w[4];
        if (has) {
            const int nn = Tn / 49;
            const int sn = (Tn % 49) * KT;
            const float* src = X + (size_t)nn * NC * SS + (size_t)row * SS + sn + coff;
            #pragma unroll
            for (int j = 0; j < 4; ++j) w[j] = *(const float4*)(src + 8 * j);
        }

        // correction = E @ xc  (fa hoisted; only fb loads per k)
        wmma::fragment<wmma::accumulator, 16, 16, 16, float> acc0, acc1;
        wmma::fill_fragment(acc0, 0.0f);
        wmma::fill_fragment(acc1, 0.0f);
        #pragma unroll
        for (int k = 0; k < 4; ++k) {
            wmma::fragment<wmma::matrix_b, 16, 16, 16, __nv_bfloat16, wmma::row_major> fb0, fb1;
            wmma::load_matrix_sync(fb0, &tb[buf][(k * 16) * BPITCH + q0], BPITCH);
            wmma::load_matrix_sync(fb1, &tb[buf][(k * 16) * BPITCH + q0 + 16], BPITCH);
            wmma::mma_sync(acc0, fa[k], fb0, acc0);
            wmma::mma_sync(acc1, fa[k], fb1, acc1);
        }
        wmma::store_matrix_sync(&scratch[warp][0],  acc0, SPITCH, wmma::mem_row_major);
        wmma::store_matrix_sync(&scratch[warp][16], acc1, SPITCH, wmma::mem_row_major);

        // center next tile + publish into the other buffer
        if (has) {
            #pragma unroll
            for (int j = 0; j < 4; ++j) {
                w[j].x -= mu; w[j].y -= mu; w[j].z -= mu; w[j].w -= mu;
                __nv_bfloat162* dst = (__nv_bfloat162*)&tb[buf ^ 1][row * BPITCH + coff + 8 * j];
                dst[0] = __floats2bfloat162_rn(w[j].x, w[j].y);
                dst[1] = __floats2bfloat162_rn(w[j].z, w[j].w);
            }
        }
        __syncwarp();   // scratch visibility within the warp

        // epilogue (fully warp-local): out = xc(regs) + corr(scratch)
        {
            float* Yp = Y + (size_t)n * NC * SS + (size_t)row * SS + s0 + coff;
            #pragma unroll
            for (int j = 0; j < 4; ++j) {
                float4 c = *(const float4*)(scp + 8 * j);
                c.x += cur[j].x; c.y += cur[j].y; c.z += cur[j].z; c.w += cur[j].w;
                *(float4*)(Yp + 8 * j) = c;
            }
        }

        #pragma unroll
        for (int j = 0; j < 4; ++j) cur[j] = w[j];
        __syncthreads();   // tb[buf^1] published; tb[buf] fully consumed
    }
}

// ---------------------------------------------------------------------------
extern "C" void kernel_launch(void* const* d_in, const int* in_sizes, int n_in,
                              void* d_out, int out_size) {
    (void)in_sizes; (void)n_in; (void)out_size;
    const float* X = (const float*)d_in[0];
    float* Y = (float*)d_out;

    gram_kernel<<<GRID, 256>>>(X);
    reduce_kernel<<<5, 256>>>();
    stats_kernel<<<1, 256>>>();
    whiten_kernel<<<GRID, 256>>>(X, Y);
}